// round 1
// baseline (speedup 1.0000x reference)
#include <cuda_runtime.h>

#define IN_F 8192
#define OUT_F 8192
#define THRESH_F 50.0f
#define ROWS_PER_BLOCK 8
#define THREADS 256

// Scratch for current[] between kernels (no allocations allowed).
__device__ float g_current[OUT_F];

// Kernel 1: binarized matvec + spike decision.
// grid = OUT_F / ROWS_PER_BLOCK blocks, 256 threads (8 warps), 1 row per warp.
__global__ void __launch_bounds__(THREADS) snn_matvec_kernel(
    const float* __restrict__ spike_input,   // [IN_F]
    const float* __restrict__ syn,           // [OUT_F, IN_F] row-major
    const float* __restrict__ v_mem,         // [OUT_F]
    const float* __restrict__ v_th,          // [OUT_F]
    const float* __restrict__ noise,         // [OUT_F]
    float* __restrict__ out)                 // out[0:OUT_F] = spikes
{
    __shared__ float4 s_spike[IN_F / 4];     // 32 KB

    const int tid = threadIdx.x;

    // Stage spike vector into shared (reused by all 8 rows in this block).
    const float4* sp4 = reinterpret_cast<const float4*>(spike_input);
    #pragma unroll
    for (int i = 0; i < (IN_F / 4) / THREADS; i++) {
        s_spike[tid + i * THREADS] = sp4[tid + i * THREADS];
    }
    __syncthreads();

    const int warp = tid >> 5;
    const int lane = tid & 31;
    const int row  = blockIdx.x * ROWS_PER_BLOCK + warp;

    const float4* r4 = reinterpret_cast<const float4*>(syn + (size_t)row * IN_F);

    float acc = 0.0f;
    // 2048 float4 per row / 32 lanes = 64 iterations per lane.
    #pragma unroll 8
    for (int it = 0; it < (IN_F / 4) / 32; it++) {
        const int idx = it * 32 + lane;
        const float4 w = r4[idx];
        const float4 s = s_spike[idx];
        acc += (w.x > THRESH_F) ? s.x : 0.0f;
        acc += (w.y > THRESH_F) ? s.y : 0.0f;
        acc += (w.z > THRESH_F) ? s.z : 0.0f;
        acc += (w.w > THRESH_F) ? s.w : 0.0f;
    }

    // Warp reduce (exact: small integers).
    #pragma unroll
    for (int o = 16; o > 0; o >>= 1) {
        acc += __shfl_xor_sync(0xFFFFFFFFu, acc, o);
    }

    if (lane == 0) {
        g_current[row] = acc;
        const float pot = v_mem[row] + acc + noise[row];
        out[row] = (pot >= v_th[row]) ? 1.0f : 0.0f;
    }
}

// Kernel 2: global inhibition reduction + state updates.
// Single block, 1024 threads, 8 elements per thread.
__global__ void __launch_bounds__(1024) snn_update_kernel(
    const float* __restrict__ v_mem,
    const float* __restrict__ v_th,
    float* __restrict__ out)   // [spikes | v_mem_new | v_th_new]
{
    __shared__ float red[32];

    const int tid = threadIdx.x;

    float sp[8];
    float local = 0.0f;
    #pragma unroll
    for (int i = 0; i < 8; i++) {
        sp[i] = out[tid + i * 1024];
        local += sp[i];
    }

    // Warp reduce.
    #pragma unroll
    for (int o = 16; o > 0; o >>= 1) {
        local += __shfl_xor_sync(0xFFFFFFFFu, local, o);
    }
    if ((tid & 31) == 0) red[tid >> 5] = local;
    __syncthreads();

    if (tid < 32) {
        float v = red[tid];   // exactly 32 warps
        #pragma unroll
        for (int o = 16; o > 0; o >>= 1) {
            v += __shfl_xor_sync(0xFFFFFFFFu, v, o);
        }
        if (tid == 0) red[0] = v;
    }
    __syncthreads();

    const float inhibition = red[0] * 0.5f;

    #pragma unroll
    for (int i = 0; i < 8; i++) {
        const int o = tid + i * 1024;
        const float s   = sp[i];
        const float cur = g_current[o];
        const float vm  = v_mem[o];

        const float v_new = (vm - inhibition + cur) * (1.0f - s) * 0.5f;

        float vt = v_th[o] + (s - 0.1f) * 0.01f;
        vt = fminf(fmaxf(vt, 0.2f), 5.0f);

        out[OUT_F + o]     = v_new;
        out[2 * OUT_F + o] = vt;
    }
}

extern "C" void kernel_launch(void* const* d_in, const int* in_sizes, int n_in,
                              void* d_out, int out_size)
{
    const float* spike_input = (const float*)d_in[0];   // [1, 8192]
    const float* syn         = (const float*)d_in[1];   // [8192, 8192]
    const float* v_mem       = (const float*)d_in[2];   // [8192]
    const float* v_th        = (const float*)d_in[3];   // [8192]
    const float* noise       = (const float*)d_in[4];   // [8192]
    float* out = (float*)d_out;                          // 3 * 8192 floats

    snn_matvec_kernel<<<OUT_F / ROWS_PER_BLOCK, THREADS>>>(
        spike_input, syn, v_mem, v_th, noise, out);
    snn_update_kernel<<<1, 1024>>>(v_mem, v_th, out);
}

// round 2
// speedup vs baseline: 1.2507x; 1.2507x over previous
#include <cuda_runtime.h>

#define IN_F 8192
#define OUT_F 8192
#define THRESH_F 50.0f
#define ROWS_PER_BLOCK 8
#define THREADS 256
#define UPD_BLOCKS 32
#define UPD_THREADS 256

// Scratch for current[] between kernels (no allocations allowed).
__device__ float g_current[OUT_F];

// Kernel 1: binarized matvec + spike decision.
// grid = OUT_F / ROWS_PER_BLOCK blocks, 256 threads (8 warps), 1 row per warp.
__global__ void __launch_bounds__(THREADS) snn_matvec_kernel(
    const float* __restrict__ spike_input,   // [IN_F]
    const float* __restrict__ syn,           // [OUT_F, IN_F] row-major
    const float* __restrict__ v_mem,         // [OUT_F]
    const float* __restrict__ v_th,          // [OUT_F]
    const float* __restrict__ noise,         // [OUT_F]
    float* __restrict__ out)                 // out[0:OUT_F] = spikes
{
    __shared__ float4 s_spike[IN_F / 4];     // 32 KB

    const int tid = threadIdx.x;

    // Stage spike vector into shared (reused by all 8 rows in this block).
    const float4* sp4 = reinterpret_cast<const float4*>(spike_input);
    #pragma unroll
    for (int i = 0; i < (IN_F / 4) / THREADS; i++) {
        s_spike[tid + i * THREADS] = sp4[tid + i * THREADS];
    }
    __syncthreads();

    const int warp = tid >> 5;
    const int lane = tid & 31;
    const int row  = blockIdx.x * ROWS_PER_BLOCK + warp;

    const float4* r4 = reinterpret_cast<const float4*>(syn + (size_t)row * IN_F);

    float acc0 = 0.0f, acc1 = 0.0f;
    // 2048 float4 per row / 32 lanes = 64 float4 per lane; 2 per iteration.
    #pragma unroll 8
    for (int it = 0; it < (IN_F / 8) / 32; it++) {
        const int i0 = (it * 2 + 0) * 32 + lane;
        const int i1 = (it * 2 + 1) * 32 + lane;
        const float4 w0 = r4[i0];
        const float4 w1 = r4[i1];
        const float4 s0 = s_spike[i0];
        const float4 s1 = s_spike[i1];
        if (w0.x > THRESH_F) acc0 += s0.x;
        if (w0.y > THRESH_F) acc1 += s0.y;
        if (w0.z > THRESH_F) acc0 += s0.z;
        if (w0.w > THRESH_F) acc1 += s0.w;
        if (w1.x > THRESH_F) acc0 += s1.x;
        if (w1.y > THRESH_F) acc1 += s1.y;
        if (w1.z > THRESH_F) acc0 += s1.z;
        if (w1.w > THRESH_F) acc1 += s1.w;
    }
    float acc = acc0 + acc1;

    // Warp reduce (exact: small integers).
    #pragma unroll
    for (int o = 16; o > 0; o >>= 1) {
        acc += __shfl_xor_sync(0xFFFFFFFFu, acc, o);
    }

    if (lane == 0) {
        g_current[row] = acc;
        const float pot = v_mem[row] + acc + noise[row];
        out[row] = (pot >= v_th[row]) ? 1.0f : 0.0f;
    }
}

// Kernel 2: state updates. Every block redundantly computes the full spike
// sum (exact: integer-valued floats), then updates its own 256-row slice.
// No atomics, no persistent scratch state across graph replays.
__global__ void __launch_bounds__(UPD_THREADS) snn_update_kernel(
    const float* __restrict__ v_mem,
    const float* __restrict__ v_th,
    float* __restrict__ out)   // [spikes | v_mem_new | v_th_new]
{
    __shared__ float red[8];

    const int tid = threadIdx.x;

    // Full spike sum: 8192 floats, 8 float4 loads per thread.
    const float4* sp4 = reinterpret_cast<const float4*>(out);
    float local = 0.0f;
    #pragma unroll
    for (int i = 0; i < (OUT_F / 4) / UPD_THREADS; i++) {
        const float4 v = sp4[tid + i * UPD_THREADS];
        local += (v.x + v.y) + (v.z + v.w);
    }
    #pragma unroll
    for (int o = 16; o > 0; o >>= 1) {
        local += __shfl_xor_sync(0xFFFFFFFFu, local, o);
    }
    if ((tid & 31) == 0) red[tid >> 5] = local;
    __syncthreads();

    float total = red[0];
    #pragma unroll
    for (int w = 1; w < UPD_THREADS / 32; w++) total += red[w];

    const float inhibition = total * 0.5f;

    // This block's slice: 256 rows, one per thread.
    const int o = blockIdx.x * UPD_THREADS + tid;
    const float s   = out[o];
    const float cur = g_current[o];
    const float vm  = v_mem[o];

    const float v_new = (vm - inhibition + cur) * (1.0f - s) * 0.5f;

    float vt = v_th[o] + (s - 0.1f) * 0.01f;
    vt = fminf(fmaxf(vt, 0.2f), 5.0f);

    out[OUT_F + o]     = v_new;
    out[2 * OUT_F + o] = vt;
}

extern "C" void kernel_launch(void* const* d_in, const int* in_sizes, int n_in,
                              void* d_out, int out_size)
{
    const float* spike_input = (const float*)d_in[0];   // [1, 8192]
    const float* syn         = (const float*)d_in[1];   // [8192, 8192]
    const float* v_mem       = (const float*)d_in[2];   // [8192]
    const float* v_th        = (const float*)d_in[3];   // [8192]
    const float* noise       = (const float*)d_in[4];   // [8192]
    float* out = (float*)d_out;                          // 3 * 8192 floats

    snn_matvec_kernel<<<OUT_F / ROWS_PER_BLOCK, THREADS>>>(
        spike_input, syn, v_mem, v_th, noise, out);
    snn_update_kernel<<<UPD_BLOCKS, UPD_THREADS>>>(v_mem, v_th, out);
}